// round 1
// baseline (speedup 1.0000x reference)
#include <cuda_runtime.h>
#include <math.h>

#define B_  8
#define T_  10
#define N_  50
#define IN_ 6
#define H_  256
#define K_  4
#define E_  2450           // N*(N-1)
#define BN  400            // B*N
#define BE  19600          // B*E

// ---------------- scratch (device globals: no runtime allocation) ----------
__device__ float g_hidden[BN * H_];
__device__ float g_ins[BN * IN_];
__device__ float g_U[6 * BN * H_];      // (type-1)*2 + {recv=0,send=1}
__device__ float g_M1[3 * BE * H_];     // tanh(first layer) per edge type
__device__ float g_msgs[BE * H_];       // weighted sum of second-layer msgs
__device__ float g_agg[BN * H_];
__device__ float g_gru[3 * BN * H_];    // agg @ {w_hr,w_hi,w_hh}.T
__device__ float g_p1[BN * H_];
__device__ float g_p2[BN * H_];

// ---------------- f32x2 packed FMA helpers ---------------------------------
__device__ __forceinline__ unsigned long long pk2(float x) {
    unsigned long long r; unsigned int u = __float_as_uint(x);
    asm("mov.b64 %0, {%1,%1};" : "=l"(r) : "r"(u));
    return r;
}
__device__ __forceinline__ unsigned long long ffma2(unsigned long long a,
                                                    unsigned long long b,
                                                    unsigned long long c) {
    unsigned long long r;
    asm("fma.rn.f32x2 %0, %1, %2, %3;" : "=l"(r) : "l"(a), "l"(b), "l"(c));
    return r;
}
__device__ __forceinline__ void upk2(unsigned long long v, float& lo, float& hi) {
    unsigned int a, b;
    asm("mov.b64 {%0,%1}, %2;" : "=r"(a), "=r"(b) : "l"(v));
    lo = __uint_as_float(a); hi = __uint_as_float(b);
}

// ---------------- shared 64x64x16 GEMM body (C = A @ W^T) ------------------
// A: [M,K] row-major (lda), W: [N,K] row-major (ldw). 256 threads, 4x4/thread.
__device__ __forceinline__ void gemm_body(
    const float* __restrict__ A, int lda,
    const float* __restrict__ W, int ldw,
    const float* __restrict__ bias,
    float* __restrict__ C, int ldc,
    int M, int N, int K, int act /*0=none,1=relu*/)
{
    __shared__ __align__(16) float As[16][65];
    __shared__ __align__(16) float Ws[16][66];
    const int tid = threadIdx.x;
    const int row0 = blockIdx.x * 64, col0 = blockIdx.y * 64;
    const int ty = tid >> 4, tx = tid & 15;
    const int lr = tid >> 2, lk = (tid & 3) << 2;

    unsigned long long acc[4][2];
#pragma unroll
    for (int m = 0; m < 4; m++) { acc[m][0] = 0ULL; acc[m][1] = 0ULL; }

    for (int k0 = 0; k0 < K; k0 += 16) {
        float4 av = make_float4(0.f, 0.f, 0.f, 0.f);
        int ar = row0 + lr;
        if (ar < M) av = *(const float4*)(A + (size_t)ar * lda + k0 + lk);
        As[lk + 0][lr] = av.x; As[lk + 1][lr] = av.y;
        As[lk + 2][lr] = av.z; As[lk + 3][lr] = av.w;

        float4 wv = make_float4(0.f, 0.f, 0.f, 0.f);
        int wc = col0 + lr;
        if (wc < N) wv = *(const float4*)(W + (size_t)wc * ldw + k0 + lk);
        Ws[lk + 0][lr] = wv.x; Ws[lk + 1][lr] = wv.y;
        Ws[lk + 2][lr] = wv.z; Ws[lk + 3][lr] = wv.w;
        __syncthreads();
#pragma unroll
        for (int kk = 0; kk < 16; kk++) {
            unsigned long long b0 = *(const unsigned long long*)&Ws[kk][tx * 4];
            unsigned long long b1 = *(const unsigned long long*)&Ws[kk][tx * 4 + 2];
#pragma unroll
            for (int m = 0; m < 4; m++) {
                unsigned long long aa = pk2(As[kk][ty * 4 + m]);
                acc[m][0] = ffma2(aa, b0, acc[m][0]);
                acc[m][1] = ffma2(aa, b1, acc[m][1]);
            }
        }
        __syncthreads();
    }
#pragma unroll
    for (int m = 0; m < 4; m++) {
        int r = row0 + ty * 4 + m;
        if (r >= M) continue;
        float o0, o1, o2, o3;
        upk2(acc[m][0], o0, o1);
        upk2(acc[m][1], o2, o3);
        float outv[4] = {o0, o1, o2, o3};
#pragma unroll
        for (int c = 0; c < 4; c++) {
            int cc = col0 + tx * 4 + c;
            if (cc >= N) continue;
            float v = outv[c];
            if (bias) v += bias[cc];
            if (act == 1) v = fmaxf(v, 0.f);
            C[(size_t)r * ldc + cc] = v;
        }
    }
}

// ---------------- kernels ---------------------------------------------------

// init: hidden = 0, ins = inputs[:, 0]
__global__ void init_kernel(const float* __restrict__ inputs) {
    int idx = blockIdx.x * blockDim.x + threadIdx.x;
    if (idx < BN * H_) g_hidden[idx] = 0.f;
    if (idx < BN * IN_) {
        int row = idx / IN_, c = idx % IN_;
        int b = row / N_, n = row % N_;
        g_ins[idx] = inputs[(((size_t)b * T_ + 0) * N_ + n) * IN_ + c];
    }
}

// Ur/Us: grid (7, 4, 6): z = (type-1)*2 + rs
__global__ __launch_bounds__(256)
void urus_kernel(const float* __restrict__ msg_w1) {
    int z = blockIdx.z;
    int it = z >> 1, rs = z & 1;
    const float* W = msg_w1 + (size_t)(it + 1) * H_ * 2 * H_ + rs * H_;
    gemm_body(g_hidden, H_, W, 2 * H_, nullptr,
              g_U + (size_t)z * BN * H_, H_, BN, H_, H_, 0);
}

// M1[i][row,h] = tanh(Ur[recv] + Us[send] + b1)   (float4-vectorized)
__global__ void m1_kernel(const float* __restrict__ msg_b1) {
    int idx = blockIdx.x * blockDim.x + threadIdx.x;
    const int per_type = BE * (H_ / 4);
    if (idx >= 3 * per_type) return;
    int i = idx / per_type;
    int rem = idx - i * per_type;
    int row = rem / (H_ / 4);
    int h4 = rem - row * (H_ / 4);
    int b = row / E_, e = row - b * E_;
    int send = e / 49, rr = e - send * 49;
    int recv = rr + (rr >= send);
    const float4 ur = *(const float4*)(g_U + ((size_t)(i * 2) * BN + b * N_ + recv) * H_ + h4 * 4);
    const float4 us = *(const float4*)(g_U + ((size_t)(i * 2 + 1) * BN + b * N_ + send) * H_ + h4 * 4);
    const float4 bv = *(const float4*)(msg_b1 + (size_t)(i + 1) * H_ + h4 * 4);
    float4 o;
    o.x = tanhf(ur.x + us.x + bv.x);
    o.y = tanhf(ur.y + us.y + bv.y);
    o.z = tanhf(ur.z + us.z + bv.z);
    o.w = tanhf(ur.w + us.w + bv.w);
    *(float4*)(g_M1 + ((size_t)i * BE + row) * H_ + h4 * 4) = o;
}

// msgs[row,:] = sum_i tanh(M1[i][row] @ W2[i].T + b2[i]) * rel[row,i] / 3
__global__ __launch_bounds__(256)
void msgs_kernel(const float* __restrict__ msg_w2,
                 const float* __restrict__ msg_b2,
                 const float* __restrict__ edges, int t) {
    __shared__ __align__(16) float As[16][65];
    __shared__ __align__(16) float Ws[16][66];
    __shared__ float relw[64];
    const int tid = threadIdx.x;
    const int row0 = blockIdx.x * 64, col0 = blockIdx.y * 64;
    const int ty = tid >> 4, tx = tid & 15;
    const int lr = tid >> 2, lk = (tid & 3) << 2;

    float tot[4][4] = {};
    for (int i = 0; i < 3; i++) {
        const int type = i + 1;
        __syncthreads();   // prior epilogue done reading relw
        if (tid < 64) {
            int r = row0 + tid;
            float rv = 0.f;
            if (r < BE) {
                int b = r / E_, e = r - b * E_;
                rv = edges[(((size_t)b * T_ + t) * E_ + e) * K_ + type] * (1.f / 3.f);
            }
            relw[tid] = rv;
        }
        unsigned long long acc[4][2];
#pragma unroll
        for (int m = 0; m < 4; m++) { acc[m][0] = 0ULL; acc[m][1] = 0ULL; }

        const float* Ai = g_M1 + (size_t)i * BE * H_;
        const float* Wi = msg_w2 + (size_t)type * H_ * H_;
        for (int k0 = 0; k0 < H_; k0 += 16) {
            float4 av = make_float4(0.f, 0.f, 0.f, 0.f);
            int ar = row0 + lr;
            if (ar < BE) av = *(const float4*)(Ai + (size_t)ar * H_ + k0 + lk);
            As[lk + 0][lr] = av.x; As[lk + 1][lr] = av.y;
            As[lk + 2][lr] = av.z; As[lk + 3][lr] = av.w;
            float4 wv = *(const float4*)(Wi + (size_t)(col0 + lr) * H_ + k0 + lk);
            Ws[lk + 0][lr] = wv.x; Ws[lk + 1][lr] = wv.y;
            Ws[lk + 2][lr] = wv.z; Ws[lk + 3][lr] = wv.w;
            __syncthreads();
#pragma unroll
            for (int kk = 0; kk < 16; kk++) {
                unsigned long long b0 = *(const unsigned long long*)&Ws[kk][tx * 4];
                unsigned long long b1 = *(const unsigned long long*)&Ws[kk][tx * 4 + 2];
#pragma unroll
                for (int m = 0; m < 4; m++) {
                    unsigned long long aa = pk2(As[kk][ty * 4 + m]);
                    acc[m][0] = ffma2(aa, b0, acc[m][0]);
                    acc[m][1] = ffma2(aa, b1, acc[m][1]);
                }
            }
            __syncthreads();
        }
        float bb[4];
#pragma unroll
        for (int c = 0; c < 4; c++)
            bb[c] = msg_b2[(size_t)type * H_ + col0 + tx * 4 + c];
#pragma unroll
        for (int m = 0; m < 4; m++) {
            float rl = relw[ty * 4 + m];
            float o0, o1, o2, o3;
            upk2(acc[m][0], o0, o1);
            upk2(acc[m][1], o2, o3);
            tot[m][0] += tanhf(o0 + bb[0]) * rl;
            tot[m][1] += tanhf(o1 + bb[1]) * rl;
            tot[m][2] += tanhf(o2 + bb[2]) * rl;
            tot[m][3] += tanhf(o3 + bb[3]) * rl;
        }
    }
#pragma unroll
    for (int m = 0; m < 4; m++) {
        int r = row0 + ty * 4 + m;
        if (r >= BE) continue;
#pragma unroll
        for (int c = 0; c < 4; c++)
            g_msgs[(size_t)r * H_ + col0 + tx * 4 + c] = tot[m][c];
    }
}

// agg[b,r,:] = (1/49) * sum_{send != r} msgs[b, e(send,r), :]
__global__ void agg_kernel() {
    int idx = blockIdx.x * blockDim.x + threadIdx.x;
    if (idx >= BN * (H_ / 4)) return;
    int b = idx / (N_ * (H_ / 4));
    int rem = idx - b * (N_ * (H_ / 4));
    int r = rem / (H_ / 4);
    int h4 = rem - r * (H_ / 4);
    const float* base = g_msgs + (size_t)b * E_ * H_ + h4 * 4;
    float4 s = make_float4(0.f, 0.f, 0.f, 0.f);
    for (int send = 0; send < N_; send++) {
        if (send == r) continue;
        int e = send * 49 + r - (r > send);
        float4 v = *(const float4*)(base + (size_t)e * H_);
        s.x += v.x; s.y += v.y; s.z += v.z; s.w += v.w;
    }
    const float inv = 1.f / 49.f;
    s.x *= inv; s.y *= inv; s.z *= inv; s.w *= inv;
    *(float4*)(g_agg + (size_t)idx * 4) = s;
}

// GRU hidden-side GEMMs: grid (7,4,3)
__global__ __launch_bounds__(256)
void gru_gemm(const float* __restrict__ w_hr,
              const float* __restrict__ w_hi,
              const float* __restrict__ w_hh) {
    int z = blockIdx.z;
    const float* W = (z == 0) ? w_hr : (z == 1) ? w_hi : w_hh;
    gemm_body(g_agg, H_, W, H_, nullptr,
              g_gru + (size_t)z * BN * H_, H_, BN, H_, H_, 0);
}

__device__ __forceinline__ float sigmoidf_(float x) { return 1.f / (1.f + expf(-x)); }

// GRU elementwise update
__global__ void gruew_kernel(const float* __restrict__ w_ir, const float* __restrict__ b_ir,
                             const float* __restrict__ w_ii, const float* __restrict__ b_ii,
                             const float* __restrict__ w_in, const float* __restrict__ b_in) {
    int idx = blockIdx.x * blockDim.x + threadIdx.x;
    if (idx >= BN * H_) return;
    int row = idx / H_, h = idx - row * H_;
    float xr = b_ir[h], xi = b_ii[h], xn = b_in[h];
#pragma unroll
    for (int f = 0; f < IN_; f++) {
        float iv = g_ins[row * IN_ + f];
        xr += iv * w_ir[h * IN_ + f];
        xi += iv * w_ii[h * IN_ + f];
        xn += iv * w_in[h * IN_ + f];
    }
    float ar = g_gru[idx];
    float ai = g_gru[BN * H_ + idx];
    float ah = g_gru[2 * BN * H_ + idx];
    float r  = sigmoidf_(xr + ar);
    float ig = sigmoidf_(xi + ai);
    float nn = tanhf(xn + r * ah);
    g_hidden[idx] = (1.f - ig) * nn + ig * g_hidden[idx];
}

// output MLP layer 1 / 2
__global__ __launch_bounds__(256)
void p1_gemm(const float* __restrict__ w_o1, const float* __restrict__ b_o1) {
    gemm_body(g_hidden, H_, w_o1, H_, b_o1, g_p1, H_, BN, H_, H_, 1);
}
__global__ __launch_bounds__(256)
void p2_gemm(const float* __restrict__ w_o2, const float* __restrict__ b_o2) {
    gemm_body(g_p1, H_, w_o2, H_, b_o2, g_p2, H_, BN, H_, H_, 1);
}

// pred = ins + p2 @ w_o3.T + b_o3; write out[:,t] and next ins
__global__ void f3_kernel(const float* __restrict__ w_o3,
                          const float* __restrict__ b_o3,
                          float* __restrict__ out, int t) {
    int row = blockIdx.x;                 // 0..399
    int w = threadIdx.x >> 5;             // 0..5 (output channel)
    int lane = threadIdx.x & 31;
    const float* pr = g_p2 + (size_t)row * H_;
    const float* wr = w_o3 + (size_t)w * H_;
    float s = 0.f;
    for (int j = lane; j < H_; j += 32) s += pr[j] * wr[j];
#pragma unroll
    for (int off = 16; off; off >>= 1) s += __shfl_down_sync(0xffffffffu, s, off);
    if (lane == 0) {
        int b = row / N_, n = row % N_;
        float v = g_ins[row * IN_ + w] + b_o3[w] + s;
        out[(((size_t)b * T_ + t) * N_ + n) * IN_ + w] = v;
        g_ins[row * IN_ + w] = v;
    }
}

// ---------------- launch ----------------------------------------------------
extern "C" void kernel_launch(void* const* d_in, const int* in_sizes, int n_in,
                              void* d_out, int out_size) {
    const float* inputs = (const float*)d_in[0];
    const float* edges  = (const float*)d_in[1];
    const float* msg_w1 = (const float*)d_in[2];
    const float* msg_b1 = (const float*)d_in[3];
    const float* msg_w2 = (const float*)d_in[4];
    const float* msg_b2 = (const float*)d_in[5];
    const float* w_hr = (const float*)d_in[6];
    const float* w_hi = (const float*)d_in[7];
    const float* w_hh = (const float*)d_in[8];
    const float* w_ir = (const float*)d_in[9];
    const float* b_ir = (const float*)d_in[10];
    const float* w_ii = (const float*)d_in[11];
    const float* b_ii = (const float*)d_in[12];
    const float* w_in_ = (const float*)d_in[13];
    const float* b_in_ = (const float*)d_in[14];
    const float* w_o1 = (const float*)d_in[15];
    const float* b_o1 = (const float*)d_in[16];
    const float* w_o2 = (const float*)d_in[17];
    const float* b_o2 = (const float*)d_in[18];
    const float* w_o3 = (const float*)d_in[19];
    const float* b_o3 = (const float*)d_in[20];
    float* out = (float*)d_out;

    init_kernel<<<(BN * H_ + 255) / 256, 256>>>(inputs);

    const int m1_total = 3 * BE * (H_ / 4);
    for (int t = 0; t < T_; t++) {
        urus_kernel<<<dim3(7, 4, 6), 256>>>(msg_w1);
        m1_kernel<<<(m1_total + 255) / 256, 256>>>(msg_b1);
        msgs_kernel<<<dim3((BE + 63) / 64, 4), 256>>>(msg_w2, msg_b2, edges, t);
        agg_kernel<<<(BN * (H_ / 4) + 255) / 256, 256>>>();
        gru_gemm<<<dim3(7, 4, 3), 256>>>(w_hr, w_hi, w_hh);
        gruew_kernel<<<(BN * H_ + 255) / 256, 256>>>(w_ir, b_ir, w_ii, b_ii, w_in_, b_in_);
        p1_gemm<<<dim3(7, 4), 256>>>(w_o1, b_o1);
        p2_gemm<<<dim3(7, 4), 256>>>(w_o2, b_o2);
        f3_kernel<<<BN, 192>>>(w_o3, b_o3, out, t);
    }
}

// round 2
// speedup vs baseline: 1.1032x; 1.1032x over previous
#include <cuda_runtime.h>
#include <math.h>

#define B_  8
#define T_  10
#define N_  50
#define IN_ 6
#define H_  256
#define K_  4
#define E_  2450           // N*(N-1)
#define BN  400            // B*N
#define BE  19600          // B*E

// ---------------- scratch (device globals) ----------------------------------
__device__ float g_hidden[BN * H_];
__device__ float g_ins[BN * IN_];
__device__ float g_U[6 * BN * H_];          // (type-1)*2 + {recv=0,send=1}
__device__ float g_M1[3 * BE * H_];         // tanh(first layer) per edge type
__device__ float g_msgs3[3 * BE * H_];      // per-type weighted second-layer msgs
__device__ float g_agg[BN * H_];
__device__ float g_gru[3 * BN * H_];
__device__ float g_p1[BN * H_];
__device__ float g_p2[BN * H_];

// ---------------- f32x2 packed FMA helpers ----------------------------------
typedef unsigned long long ull;
__device__ __forceinline__ ull pk2(float x) {
    ull r; unsigned int u = __float_as_uint(x);
    asm("mov.b64 %0, {%1,%1};" : "=l"(r) : "r"(u));
    return r;
}
__device__ __forceinline__ ull ffma2(ull a, ull b, ull c) {
    ull r;
    asm("fma.rn.f32x2 %0, %1, %2, %3;" : "=l"(r) : "l"(a), "l"(b), "l"(c));
    return r;
}
__device__ __forceinline__ void upk2(ull v, float& lo, float& hi) {
    unsigned int a, b;
    asm("mov.b64 {%0,%1}, %2;" : "=r"(a), "=r"(b) : "l"(v));
    lo = __uint_as_float(a); hi = __uint_as_float(b);
}

// ---------------- 64x128 GEMM core (C = A @ W^T), 128 threads ---------------
// Per-thread 8(m) x 8(n); acc packed as ull[8][4]. A:[M,K] lda, W:[N,K] ldw.
// Requires K % 16 == 0, col0+128 <= N (exact column tiles).
__device__ __forceinline__ void gemm64_core(
    const float* __restrict__ A, int lda,
    const float* __restrict__ W, int ldw,
    int M, int K, int row0, int col0,
    ull acc[8][4],
    float As[16][68], float Ws[16][132])
{
    const int tid = threadIdx.x;
    const int tx = tid & 15, ty = tid >> 4;
    const int lr = tid >> 1, lk = (tid & 1) * 8;

    for (int k0 = 0; k0 < K; k0 += 16) {
        // stage A (64 rows x 16 k)
        float4 a0 = make_float4(0.f,0.f,0.f,0.f), a1 = a0;
        int ar = row0 + lr;
        if (ar < M) {
            const float* Ap = A + (size_t)ar * lda + k0 + lk;
            a0 = *(const float4*)Ap;
            a1 = *(const float4*)(Ap + 4);
        }
        As[lk+0][lr]=a0.x; As[lk+1][lr]=a0.y; As[lk+2][lr]=a0.z; As[lk+3][lr]=a0.w;
        As[lk+4][lr]=a1.x; As[lk+5][lr]=a1.y; As[lk+6][lr]=a1.z; As[lk+7][lr]=a1.w;

        // stage W (128 rows x 16 k)
        const float* Wp0 = W + (size_t)(col0 + lr) * ldw + k0 + lk;
        const float* Wp1 = W + (size_t)(col0 + lr + 64) * ldw + k0 + lk;
        float4 w0 = *(const float4*)Wp0, w1 = *(const float4*)(Wp0 + 4);
        float4 w2 = *(const float4*)Wp1, w3 = *(const float4*)(Wp1 + 4);
        Ws[lk+0][lr]=w0.x; Ws[lk+1][lr]=w0.y; Ws[lk+2][lr]=w0.z; Ws[lk+3][lr]=w0.w;
        Ws[lk+4][lr]=w1.x; Ws[lk+5][lr]=w1.y; Ws[lk+6][lr]=w1.z; Ws[lk+7][lr]=w1.w;
        Ws[lk+0][lr+64]=w2.x; Ws[lk+1][lr+64]=w2.y; Ws[lk+2][lr+64]=w2.z; Ws[lk+3][lr+64]=w2.w;
        Ws[lk+4][lr+64]=w3.x; Ws[lk+5][lr+64]=w3.y; Ws[lk+6][lr+64]=w3.z; Ws[lk+7][lr+64]=w3.w;
        __syncthreads();

#pragma unroll
        for (int kk = 0; kk < 16; kk++) {
            const float4 af0 = *(const float4*)&As[kk][ty * 8];
            const float4 af1 = *(const float4*)&As[kk][ty * 8 + 4];
            const ull b0 = *(const ull*)&Ws[kk][tx * 8];
            const ull b1 = *(const ull*)&Ws[kk][tx * 8 + 2];
            const ull b2 = *(const ull*)&Ws[kk][tx * 8 + 4];
            const ull b3 = *(const ull*)&Ws[kk][tx * 8 + 6];
            float am[8] = {af0.x, af0.y, af0.z, af0.w, af1.x, af1.y, af1.z, af1.w};
#pragma unroll
            for (int m = 0; m < 8; m++) {
                ull aa = pk2(am[m]);
                acc[m][0] = ffma2(aa, b0, acc[m][0]);
                acc[m][1] = ffma2(aa, b1, acc[m][1]);
                acc[m][2] = ffma2(aa, b2, acc[m][2]);
                acc[m][3] = ffma2(aa, b3, acc[m][3]);
            }
        }
        __syncthreads();
    }
}

// Plain epilogue: bias + optional relu
__device__ __forceinline__ void gemm64_store(
    ull acc[8][4], const float* __restrict__ bias,
    float* __restrict__ C, int ldc, int M, int row0, int col0, int act)
{
    const int tid = threadIdx.x;
    const int tx = tid & 15, ty = tid >> 4;
#pragma unroll
    for (int m = 0; m < 8; m++) {
        int r = row0 + ty * 8 + m;
        if (r >= M) continue;
#pragma unroll
        for (int j = 0; j < 4; j++) {
            float lo, hi;
            upk2(acc[m][j], lo, hi);
            int c = col0 + tx * 8 + 2 * j;
            if (bias) { lo += bias[c]; hi += bias[c + 1]; }
            if (act == 1) { lo = fmaxf(lo, 0.f); hi = fmaxf(hi, 0.f); }
            float2 v = make_float2(lo, hi);
            *(float2*)(C + (size_t)r * ldc + c) = v;
        }
    }
}

// ---------------- kernels ----------------------------------------------------

__global__ void init_kernel(const float* __restrict__ inputs) {
    int idx = blockIdx.x * blockDim.x + threadIdx.x;
    if (idx < BN * H_) g_hidden[idx] = 0.f;
    if (idx < BN * IN_) {
        int row = idx / IN_, c = idx % IN_;
        int b = row / N_, n = row % N_;
        g_ins[idx] = inputs[(((size_t)b * T_ + 0) * N_ + n) * IN_ + c];
    }
}

// Ur/Us: grid (7, 2, 6): z = (type-1)*2 + rs
__global__ __launch_bounds__(128, 4)
void urus_kernel(const float* __restrict__ msg_w1) {
    __shared__ float As[16][68];
    __shared__ float Ws[16][132];
    int z = blockIdx.z;
    int it = z >> 1, rs = z & 1;
    const float* W = msg_w1 + (size_t)(it + 1) * H_ * 2 * H_ + rs * H_;
    ull acc[8][4];
#pragma unroll
    for (int m = 0; m < 8; m++) { acc[m][0]=0; acc[m][1]=0; acc[m][2]=0; acc[m][3]=0; }
    int row0 = blockIdx.x * 64, col0 = blockIdx.y * 128;
    gemm64_core(g_hidden, H_, W, 2 * H_, BN, H_, row0, col0, acc, As, Ws);
    gemm64_store(acc, nullptr, g_U + (size_t)z * BN * H_, H_, BN, row0, col0, 0);
}

// M1[i][row,h] = tanh(Ur[recv] + Us[send] + b1)
__global__ void m1_kernel(const float* __restrict__ msg_b1) {
    int idx = blockIdx.x * blockDim.x + threadIdx.x;
    const int per_type = BE * (H_ / 4);
    if (idx >= 3 * per_type) return;
    int i = idx / per_type;
    int rem = idx - i * per_type;
    int row = rem / (H_ / 4);
    int h4 = rem - row * (H_ / 4);
    int b = row / E_, e = row - b * E_;
    int send = e / 49, rr = e - send * 49;
    int recv = rr + (rr >= send);
    const float4 ur = *(const float4*)(g_U + ((size_t)(i * 2) * BN + b * N_ + recv) * H_ + h4 * 4);
    const float4 us = *(const float4*)(g_U + ((size_t)(i * 2 + 1) * BN + b * N_ + send) * H_ + h4 * 4);
    const float4 bv = *(const float4*)(msg_b1 + (size_t)(i + 1) * H_ + h4 * 4);
    float4 o;
    o.x = tanhf(ur.x + us.x + bv.x);
    o.y = tanhf(ur.y + us.y + bv.y);
    o.z = tanhf(ur.z + us.z + bv.z);
    o.w = tanhf(ur.w + us.w + bv.w);
    *(float4*)(g_M1 + ((size_t)i * BE + row) * H_ + h4 * 4) = o;
}

// msgs3[z][row,:] = tanh(M1[z][row] @ W2[z+1].T + b2[z+1]) * rel[row,z+1] / 3
// grid (307, 2, 3)
__global__ __launch_bounds__(128, 4)
void msgs_kernel(const float* __restrict__ msg_w2,
                 const float* __restrict__ msg_b2,
                 const float* __restrict__ edges, int t) {
    __shared__ float As[16][68];
    __shared__ float Ws[16][132];
    __shared__ float relw[64];
    const int tid = threadIdx.x;
    const int z = blockIdx.z, type = z + 1;
    const int row0 = blockIdx.x * 64, col0 = blockIdx.y * 128;

    if (tid < 64) {
        int r = row0 + tid;
        float rv = 0.f;
        if (r < BE) {
            int b = r / E_, e = r - b * E_;
            rv = edges[(((size_t)b * T_ + t) * E_ + e) * K_ + type] * (1.f / 3.f);
        }
        relw[tid] = rv;
    }

    ull acc[8][4];
#pragma unroll
    for (int m = 0; m < 8; m++) { acc[m][0]=0; acc[m][1]=0; acc[m][2]=0; acc[m][3]=0; }

    gemm64_core(g_M1 + (size_t)z * BE * H_, H_,
                msg_w2 + (size_t)type * H_ * H_, H_,
                BE, H_, row0, col0, acc, As, Ws);
    // (gemm64_core ends with __syncthreads -> relw visible)

    const int tx = tid & 15, ty = tid >> 4;
    float* Cz = g_msgs3 + (size_t)z * BE * H_;
#pragma unroll
    for (int m = 0; m < 8; m++) {
        int r = row0 + ty * 8 + m;
        if (r >= BE) continue;
        float rl = relw[ty * 8 + m];
#pragma unroll
        for (int j = 0; j < 4; j++) {
            float lo, hi;
            upk2(acc[m][j], lo, hi);
            int c = col0 + tx * 8 + 2 * j;
            float b0 = msg_b2[(size_t)type * H_ + c];
            float b1 = msg_b2[(size_t)type * H_ + c + 1];
            float2 v = make_float2(tanhf(lo + b0) * rl, tanhf(hi + b1) * rl);
            *(float2*)(Cz + (size_t)r * H_ + c) = v;
        }
    }
}

// agg[b,r,:] = (1/49) * sum_z sum_{send != r} msgs3[z][b, e(send,r), :]
__global__ void agg_kernel() {
    int idx = blockIdx.x * blockDim.x + threadIdx.x;
    if (idx >= BN * (H_ / 4)) return;
    int b = idx / (N_ * (H_ / 4));
    int rem = idx - b * (N_ * (H_ / 4));
    int r = rem / (H_ / 4);
    int h4 = rem - r * (H_ / 4);
    float4 s = make_float4(0.f, 0.f, 0.f, 0.f);
#pragma unroll
    for (int z = 0; z < 3; z++) {
        const float* base = g_msgs3 + (size_t)z * BE * H_ + (size_t)b * E_ * H_ + h4 * 4;
        for (int send = 0; send < N_; send++) {
            if (send == r) continue;
            int e = send * 49 + r - (r > send);
            float4 v = *(const float4*)(base + (size_t)e * H_);
            s.x += v.x; s.y += v.y; s.z += v.z; s.w += v.w;
        }
    }
    const float inv = 1.f / 49.f;
    s.x *= inv; s.y *= inv; s.z *= inv; s.w *= inv;
    *(float4*)(g_agg + (size_t)idx * 4) = s;
}

// GRU hidden-side GEMMs: grid (7,2,3)
__global__ __launch_bounds__(128, 4)
void gru_gemm(const float* __restrict__ w_hr,
              const float* __restrict__ w_hi,
              const float* __restrict__ w_hh) {
    __shared__ float As[16][68];
    __shared__ float Ws[16][132];
    int z = blockIdx.z;
    const float* W = (z == 0) ? w_hr : (z == 1) ? w_hi : w_hh;
    ull acc[8][4];
#pragma unroll
    for (int m = 0; m < 8; m++) { acc[m][0]=0; acc[m][1]=0; acc[m][2]=0; acc[m][3]=0; }
    int row0 = blockIdx.x * 64, col0 = blockIdx.y * 128;
    gemm64_core(g_agg, H_, W, H_, BN, H_, row0, col0, acc, As, Ws);
    gemm64_store(acc, nullptr, g_gru + (size_t)z * BN * H_, H_, BN, row0, col0, 0);
}

__device__ __forceinline__ float sigmoidf_(float x) { return 1.f / (1.f + expf(-x)); }

__global__ void gruew_kernel(const float* __restrict__ w_ir, const float* __restrict__ b_ir,
                             const float* __restrict__ w_ii, const float* __restrict__ b_ii,
                             const float* __restrict__ w_in, const float* __restrict__ b_in) {
    int idx = blockIdx.x * blockDim.x + threadIdx.x;
    if (idx >= BN * H_) return;
    int row = idx / H_, h = idx - row * H_;
    float xr = b_ir[h], xi = b_ii[h], xn = b_in[h];
#pragma unroll
    for (int f = 0; f < IN_; f++) {
        float iv = g_ins[row * IN_ + f];
        xr += iv * w_ir[h * IN_ + f];
        xi += iv * w_ii[h * IN_ + f];
        xn += iv * w_in[h * IN_ + f];
    }
    float ar = g_gru[idx];
    float ai = g_gru[BN * H_ + idx];
    float ah = g_gru[2 * BN * H_ + idx];
    float r  = sigmoidf_(xr + ar);
    float ig = sigmoidf_(xi + ai);
    float nn = tanhf(xn + r * ah);
    g_hidden[idx] = (1.f - ig) * nn + ig * g_hidden[idx];
}

__global__ __launch_bounds__(128, 4)
void p1_gemm(const float* __restrict__ w_o1, const float* __restrict__ b_o1) {
    __shared__ float As[16][68];
    __shared__ float Ws[16][132];
    ull acc[8][4];
#pragma unroll
    for (int m = 0; m < 8; m++) { acc[m][0]=0; acc[m][1]=0; acc[m][2]=0; acc[m][3]=0; }
    int row0 = blockIdx.x * 64, col0 = blockIdx.y * 128;
    gemm64_core(g_hidden, H_, w_o1, H_, BN, H_, row0, col0, acc, As, Ws);
    gemm64_store(acc, b_o1, g_p1, H_, BN, row0, col0, 1);
}
__global__ __launch_bounds__(128, 4)
void p2_gemm(const float* __restrict__ w_o2, const float* __restrict__ b_o2) {
    __shared__ float As[16][68];
    __shared__ float Ws[16][132];
    ull acc[8][4];
#pragma unroll
    for (int m = 0; m < 8; m++) { acc[m][0]=0; acc[m][1]=0; acc[m][2]=0; acc[m][3]=0; }
    int row0 = blockIdx.x * 64, col0 = blockIdx.y * 128;
    gemm64_core(g_p1, H_, w_o2, H_, BN, H_, row0, col0, acc, As, Ws);
    gemm64_store(acc, b_o2, g_p2, H_, BN, row0, col0, 1);
}

// pred = ins + p2 @ w_o3.T + b_o3; write out[:,t] and next ins
__global__ void f3_kernel(const float* __restrict__ w_o3,
                          const float* __restrict__ b_o3,
                          float* __restrict__ out, int t) {
    int row = blockIdx.x;                 // 0..399
    int w = threadIdx.x >> 5;             // 0..5
    int lane = threadIdx.x & 31;
    const float* pr = g_p2 + (size_t)row * H_;
    const float* wr = w_o3 + (size_t)w * H_;
    float s = 0.f;
    for (int j = lane; j < H_; j += 32) s += pr[j] * wr[j];
#pragma unroll
    for (int off = 16; off; off >>= 1) s += __shfl_down_sync(0xffffffffu, s, off);
    if (lane == 0) {
        int b = row / N_, n = row % N_;
        float v = g_ins[row * IN_ + w] + b_o3[w] + s;
        out[(((size_t)b * T_ + t) * N_ + n) * IN_ + w] = v;
        g_ins[row * IN_ + w] = v;
    }
}

// ---------------- launch -----------------------------------------------------
extern "C" void kernel_launch(void* const* d_in, const int* in_sizes, int n_in,
                              void* d_out, int out_size) {
    const float* inputs = (const float*)d_in[0];
    const float* edges  = (const float*)d_in[1];
    const float* msg_w1 = (const float*)d_in[2];
    const float* msg_b1 = (const float*)d_in[3];
    const float* msg_w2 = (const float*)d_in[4];
    const float* msg_b2 = (const float*)d_in[5];
    const float* w_hr = (const float*)d_in[6];
    const float* w_hi = (const float*)d_in[7];
    const float* w_hh = (const float*)d_in[8];
    const float* w_ir = (const float*)d_in[9];
    const float* b_ir = (const float*)d_in[10];
    const float* w_ii = (const float*)d_in[11];
    const float* b_ii = (const float*)d_in[12];
    const float* w_in_ = (const float*)d_in[13];
    const float* b_in_ = (const float*)d_in[14];
    const float* w_o1 = (const float*)d_in[15];
    const float* b_o1 = (const float*)d_in[16];
    const float* w_o2 = (const float*)d_in[17];
    const float* b_o2 = (const float*)d_in[18];
    const float* w_o3 = (const float*)d_in[19];
    const float* b_o3 = (const float*)d_in[20];
    float* out = (float*)d_out;

    init_kernel<<<(BN * H_ + 255) / 256, 256>>>(inputs);

    const int m1_total = 3 * BE * (H_ / 4);
    const int rowt = (BE + 63) / 64;  // 307
    for (int t = 0; t < T_; t++) {
        urus_kernel<<<dim3(7, 2, 6), 128>>>(msg_w1);
        m1_kernel<<<(m1_total + 255) / 256, 256>>>(msg_b1);
        msgs_kernel<<<dim3(rowt, 2, 3), 128>>>(msg_w2, msg_b2, edges, t);
        agg_kernel<<<(BN * (H_ / 4) + 255) / 256, 256>>>();
        gru_gemm<<<dim3(7, 2, 3), 128>>>(w_hr, w_hi, w_hh);
        gruew_kernel<<<(BN * H_ + 255) / 256, 256>>>(w_ir, b_ir, w_ii, b_ii, w_in_, b_in_);
        p1_gemm<<<dim3(7, 2), 128>>>(w_o1, b_o1);
        p2_gemm<<<dim3(7, 2), 128>>>(w_o2, b_o2);
        f3_kernel<<<BN, 192>>>(w_o3, b_o3, out, t);
    }
}

// round 3
// speedup vs baseline: 1.4856x; 1.3466x over previous
#include <cuda_runtime.h>
#include <math.h>

#define B_  8
#define T_  10
#define N_  50
#define IN_ 6
#define H_  256
#define K_  4
#define E_  2450           // N*(N-1)
#define BN  400            // B*N
#define BE  19600          // B*E

// ---------------- scratch (device globals) ----------------------------------
__device__ float g_hidden[BN * H_];
__device__ float g_ins[BN * IN_];
__device__ float g_U[6 * BN * H_];          // (type-1)*2 + {recv=0,send=1}
__device__ float g_msgs[BE * H_];           // type-summed weighted messages
__device__ float g_agg[BN * H_];
__device__ float g_gru[3 * BN * H_];
__device__ float g_p1[BN * H_];
__device__ float g_p2[BN * H_];

// ---------------- f32x2 packed FMA helpers (node GEMMs) ---------------------
typedef unsigned long long ull;
__device__ __forceinline__ ull pk2(float x) {
    ull r; unsigned int u = __float_as_uint(x);
    asm("mov.b64 %0, {%1,%1};" : "=l"(r) : "r"(u));
    return r;
}
__device__ __forceinline__ ull ffma2(ull a, ull b, ull c) {
    ull r;
    asm("fma.rn.f32x2 %0, %1, %2, %3;" : "=l"(r) : "l"(a), "l"(b), "l"(c));
    return r;
}
__device__ __forceinline__ void upk2(ull v, float& lo, float& hi) {
    unsigned int a, b;
    asm("mov.b64 {%0,%1}, %2;" : "=r"(a), "=r"(b) : "l"(v));
    lo = __uint_as_float(a); hi = __uint_as_float(b);
}

// ---------------- tf32 mma helpers ------------------------------------------
__device__ __forceinline__ unsigned tf32c(float x) {
    unsigned r; asm("cvt.rna.tf32.f32 %0, %1;" : "=r"(r) : "f"(x)); return r;
}
__device__ __forceinline__ void mma8(float c[4], const unsigned a[4],
                                     unsigned b0, unsigned b1) {
    asm volatile(
        "mma.sync.aligned.m16n8k8.row.col.f32.tf32.tf32.f32 "
        "{%0,%1,%2,%3}, {%4,%5,%6,%7}, {%8,%9}, {%0,%1,%2,%3};"
        : "+f"(c[0]), "+f"(c[1]), "+f"(c[2]), "+f"(c[3])
        : "r"(a[0]), "r"(a[1]), "r"(a[2]), "r"(a[3]), "r"(b0), "r"(b1));
}

// ---------------- 64x128 GEMM core (C = A @ W^T), 128 threads (f32x2) -------
__device__ __forceinline__ void gemm64_core(
    const float* __restrict__ A, int lda,
    const float* __restrict__ W, int ldw,
    int M, int K, int row0, int col0,
    ull acc[8][4],
    float As[16][68], float Ws[16][132])
{
    const int tid = threadIdx.x;
    const int tx = tid & 15, ty = tid >> 4;
    const int lr = tid >> 1, lk = (tid & 1) * 8;

    for (int k0 = 0; k0 < K; k0 += 16) {
        float4 a0 = make_float4(0.f,0.f,0.f,0.f), a1 = a0;
        int ar = row0 + lr;
        if (ar < M) {
            const float* Ap = A + (size_t)ar * lda + k0 + lk;
            a0 = *(const float4*)Ap;
            a1 = *(const float4*)(Ap + 4);
        }
        As[lk+0][lr]=a0.x; As[lk+1][lr]=a0.y; As[lk+2][lr]=a0.z; As[lk+3][lr]=a0.w;
        As[lk+4][lr]=a1.x; As[lk+5][lr]=a1.y; As[lk+6][lr]=a1.z; As[lk+7][lr]=a1.w;

        const float* Wp0 = W + (size_t)(col0 + lr) * ldw + k0 + lk;
        const float* Wp1 = W + (size_t)(col0 + lr + 64) * ldw + k0 + lk;
        float4 w0 = *(const float4*)Wp0, w1 = *(const float4*)(Wp0 + 4);
        float4 w2 = *(const float4*)Wp1, w3 = *(const float4*)(Wp1 + 4);
        Ws[lk+0][lr]=w0.x; Ws[lk+1][lr]=w0.y; Ws[lk+2][lr]=w0.z; Ws[lk+3][lr]=w0.w;
        Ws[lk+4][lr]=w1.x; Ws[lk+5][lr]=w1.y; Ws[lk+6][lr]=w1.z; Ws[lk+7][lr]=w1.w;
        Ws[lk+0][lr+64]=w2.x; Ws[lk+1][lr+64]=w2.y; Ws[lk+2][lr+64]=w2.z; Ws[lk+3][lr+64]=w2.w;
        Ws[lk+4][lr+64]=w3.x; Ws[lk+5][lr+64]=w3.y; Ws[lk+6][lr+64]=w3.z; Ws[lk+7][lr+64]=w3.w;
        __syncthreads();

#pragma unroll
        for (int kk = 0; kk < 16; kk++) {
            const float4 af0 = *(const float4*)&As[kk][ty * 8];
            const float4 af1 = *(const float4*)&As[kk][ty * 8 + 4];
            const ull b0 = *(const ull*)&Ws[kk][tx * 8];
            const ull b1 = *(const ull*)&Ws[kk][tx * 8 + 2];
            const ull b2 = *(const ull*)&Ws[kk][tx * 8 + 4];
            const ull b3 = *(const ull*)&Ws[kk][tx * 8 + 6];
            float am[8] = {af0.x, af0.y, af0.z, af0.w, af1.x, af1.y, af1.z, af1.w};
#pragma unroll
            for (int m = 0; m < 8; m++) {
                ull aa = pk2(am[m]);
                acc[m][0] = ffma2(aa, b0, acc[m][0]);
                acc[m][1] = ffma2(aa, b1, acc[m][1]);
                acc[m][2] = ffma2(aa, b2, acc[m][2]);
                acc[m][3] = ffma2(aa, b3, acc[m][3]);
            }
        }
        __syncthreads();
    }
}

__device__ __forceinline__ void gemm64_store(
    ull acc[8][4], const float* __restrict__ bias,
    float* __restrict__ C, int ldc, int M, int row0, int col0, int act)
{
    const int tid = threadIdx.x;
    const int tx = tid & 15, ty = tid >> 4;
#pragma unroll
    for (int m = 0; m < 8; m++) {
        int r = row0 + ty * 8 + m;
        if (r >= M) continue;
#pragma unroll
        for (int j = 0; j < 4; j++) {
            float lo, hi;
            upk2(acc[m][j], lo, hi);
            int c = col0 + tx * 8 + 2 * j;
            if (bias) { lo += bias[c]; hi += bias[c + 1]; }
            if (act == 1) { lo = fmaxf(lo, 0.f); hi = fmaxf(hi, 0.f); }
            float2 v = make_float2(lo, hi);
            *(float2*)(C + (size_t)r * ldc + c) = v;
        }
    }
}

// ---------------- kernels ----------------------------------------------------

__global__ void init_kernel(const float* __restrict__ inputs) {
    int idx = blockIdx.x * blockDim.x + threadIdx.x;
    if (idx < BN * H_) g_hidden[idx] = 0.f;
    if (idx < BN * IN_) {
        int row = idx / IN_, c = idx % IN_;
        int b = row / N_, n = row % N_;
        g_ins[idx] = inputs[(((size_t)b * T_ + 0) * N_ + n) * IN_ + c];
    }
}

// Ur/Us: grid (7, 2, 6): z = (type-1)*2 + rs
__global__ __launch_bounds__(128, 4)
void urus_kernel(const float* __restrict__ msg_w1) {
    __shared__ float As[16][68];
    __shared__ float Ws[16][132];
    int z = blockIdx.z;
    int it = z >> 1, rs = z & 1;
    const float* W = msg_w1 + (size_t)(it + 1) * H_ * 2 * H_ + rs * H_;
    ull acc[8][4];
#pragma unroll
    for (int m = 0; m < 8; m++) { acc[m][0]=0; acc[m][1]=0; acc[m][2]=0; acc[m][3]=0; }
    int row0 = blockIdx.x * 64, col0 = blockIdx.y * 128;
    gemm64_core(g_hidden, H_, W, 2 * H_, BN, H_, row0, col0, acc, As, Ws);
    gemm64_store(acc, nullptr, g_U + (size_t)z * BN * H_, H_, BN, row0, col0, 0);
}

// ======== fused edge-message kernel (tf32 tensor cores) ======================
// Block tile: 64 rows (edges) x 128 cols. 128 threads = 4 warps (2m x 2n),
// warp tile 32x64. A tile = tanh(Ur[recv]+Us[send]+b1) computed inline.
// Loops 3 edge types; tot = sum_type tanh(GEMM + b2)*rel/3 -> g_msgs.
__global__ __launch_bounds__(128)
void msgs_tc_kernel(const float* __restrict__ msg_w2,
                    const float* __restrict__ msg_b1,
                    const float* __restrict__ msg_b2,
                    const float* __restrict__ edges, int t)
{
    __shared__ unsigned As[64][20];     // [row][k-local], ld=20: conflict-free frags
    __shared__ unsigned Ws[128][20];    // [n][k-local]
    __shared__ float relw[64];
    __shared__ float b2s[128];
    __shared__ int rrow[64], srow[64], eoff[64];

    const int tid = threadIdx.x;
    const int lane = tid & 31, wid = tid >> 5;
    const int gid = lane >> 2, tig = lane & 3;
    const int wm0 = (wid >> 1) * 32, wn0 = (wid & 1) * 64;
    const int row0 = blockIdx.x * 64, col0 = blockIdx.y * 128;

    if (tid < 64) {
        int r = row0 + tid;
        int valid = (r < BE);
        if (!valid) r = BE - 1;
        int b = r / E_;
        int e = r - b * E_;
        int send = e / 49, rr2 = e - send * 49;
        int recv = rr2 + (rr2 >= send);
        srow[tid] = b * N_ + send;
        rrow[tid] = b * N_ + recv;
        eoff[tid] = valid ? (((b * T_ + t) * E_ + e) * K_) : -1;
    }
    __syncthreads();

    const int ar  = tid >> 1;           // A staging row 0..63
    const int akq = (tid & 1) * 8;      // A staging k offset {0,8}
    const int wn  = tid;                // W staging row 0..127

    float tot[2][8][4];
#pragma unroll
    for (int mi = 0; mi < 2; mi++)
#pragma unroll
        for (int ni = 0; ni < 8; ni++)
#pragma unroll
            for (int j = 0; j < 4; j++) tot[mi][ni][j] = 0.f;

    for (int z = 0; z < 3; z++) {
        const int type = z + 1;
        __syncthreads();   // previous type's epilogue done reading relw/b2s
        if (tid < 64)
            relw[tid] = (eoff[tid] >= 0) ? edges[eoff[tid] + type] * (1.f / 3.f) : 0.f;
        if (tid < 128)
            b2s[tid] = msg_b2[(size_t)type * H_ + col0 + tid];

        float acc[2][8][4];
#pragma unroll
        for (int mi = 0; mi < 2; mi++)
#pragma unroll
            for (int ni = 0; ni < 8; ni++)
#pragma unroll
                for (int j = 0; j < 4; j++) acc[mi][ni][j] = 0.f;

        const float* Ur = g_U + ((size_t)(2 * z) * BN + rrow[ar]) * H_ + akq;
        const float* Us = g_U + ((size_t)(2 * z + 1) * BN + srow[ar]) * H_ + akq;
        const float* Wb = msg_w2 + ((size_t)type * H_ + (col0 + wn)) * H_;
        const float* B1 = msg_b1 + (size_t)type * H_ + akq;

        float4 pu0, pu1, ps0, ps1, pw0, pw1, pw2, pw3, pb0, pb1;
        // prefetch chunk 0
        pu0 = *(const float4*)(Ur);     pu1 = *(const float4*)(Ur + 4);
        ps0 = *(const float4*)(Us);     ps1 = *(const float4*)(Us + 4);
        pw0 = *(const float4*)(Wb);     pw1 = *(const float4*)(Wb + 4);
        pw2 = *(const float4*)(Wb + 8); pw3 = *(const float4*)(Wb + 12);
        pb0 = *(const float4*)(B1);     pb1 = *(const float4*)(B1 + 4);

#pragma unroll 1
        for (int c = 0; c < 16; c++) {
            __syncthreads();   // buffer free (prior chunk's mma done)
            // ---- store staged A (tanh fused) + W (tf32) ----
            uint4 a0v, a1v;
            a0v.x = tf32c(tanhf(pu0.x + ps0.x + pb0.x));
            a0v.y = tf32c(tanhf(pu0.y + ps0.y + pb0.y));
            a0v.z = tf32c(tanhf(pu0.z + ps0.z + pb0.z));
            a0v.w = tf32c(tanhf(pu0.w + ps0.w + pb0.w));
            a1v.x = tf32c(tanhf(pu1.x + ps1.x + pb1.x));
            a1v.y = tf32c(tanhf(pu1.y + ps1.y + pb1.y));
            a1v.z = tf32c(tanhf(pu1.z + ps1.z + pb1.z));
            a1v.w = tf32c(tanhf(pu1.w + ps1.w + pb1.w));
            *(uint4*)&As[ar][akq]     = a0v;
            *(uint4*)&As[ar][akq + 4] = a1v;
            uint4 w0v, w1v, w2v, w3v;
            w0v.x = tf32c(pw0.x); w0v.y = tf32c(pw0.y); w0v.z = tf32c(pw0.z); w0v.w = tf32c(pw0.w);
            w1v.x = tf32c(pw1.x); w1v.y = tf32c(pw1.y); w1v.z = tf32c(pw1.z); w1v.w = tf32c(pw1.w);
            w2v.x = tf32c(pw2.x); w2v.y = tf32c(pw2.y); w2v.z = tf32c(pw2.z); w2v.w = tf32c(pw2.w);
            w3v.x = tf32c(pw3.x); w3v.y = tf32c(pw3.y); w3v.z = tf32c(pw3.z); w3v.w = tf32c(pw3.w);
            *(uint4*)&Ws[wn][0]  = w0v;
            *(uint4*)&Ws[wn][4]  = w1v;
            *(uint4*)&Ws[wn][8]  = w2v;
            *(uint4*)&Ws[wn][12] = w3v;
            __syncthreads();
            // ---- prefetch next chunk (overlaps mma) ----
            if (c < 15) {
                int k0 = (c + 1) * 16;
                pu0 = *(const float4*)(Ur + k0);     pu1 = *(const float4*)(Ur + k0 + 4);
                ps0 = *(const float4*)(Us + k0);     ps1 = *(const float4*)(Us + k0 + 4);
                pw0 = *(const float4*)(Wb + k0);     pw1 = *(const float4*)(Wb + k0 + 4);
                pw2 = *(const float4*)(Wb + k0 + 8); pw3 = *(const float4*)(Wb + k0 + 12);
                pb0 = *(const float4*)(B1 + k0);     pb1 = *(const float4*)(B1 + k0 + 4);
            }
            // ---- mma over this chunk: two k8 steps ----
#pragma unroll
            for (int kk = 0; kk < 16; kk += 8) {
                unsigned a0[4], a1[4];
                a0[0] = As[wm0 + gid][kk + tig];
                a0[1] = As[wm0 + gid + 8][kk + tig];
                a0[2] = As[wm0 + gid][kk + tig + 4];
                a0[3] = As[wm0 + gid + 8][kk + tig + 4];
                a1[0] = As[wm0 + 16 + gid][kk + tig];
                a1[1] = As[wm0 + 24 + gid][kk + tig];
                a1[2] = As[wm0 + 16 + gid][kk + tig + 4];
                a1[3] = As[wm0 + 24 + gid][kk + tig + 4];
#pragma unroll
                for (int ni = 0; ni < 8; ni++) {
                    int nr = wn0 + ni * 8 + gid;
                    unsigned b0 = Ws[nr][kk + tig];
                    unsigned b1 = Ws[nr][kk + tig + 4];
                    mma8(acc[0][ni], a0, b0, b1);
                    mma8(acc[1][ni], a1, b0, b1);
                }
            }
        }

        // ---- epilogue: tot += tanh(acc + b2) * rel ----
#pragma unroll
        for (int mi = 0; mi < 2; mi++) {
            float rl0 = relw[wm0 + mi * 16 + gid];
            float rl1 = relw[wm0 + mi * 16 + gid + 8];
#pragma unroll
            for (int ni = 0; ni < 8; ni++) {
                int cl = wn0 + ni * 8 + tig * 2;
                float bb0 = b2s[cl], bb1 = b2s[cl + 1];
                tot[mi][ni][0] += tanhf(acc[mi][ni][0] + bb0) * rl0;
                tot[mi][ni][1] += tanhf(acc[mi][ni][1] + bb1) * rl0;
                tot[mi][ni][2] += tanhf(acc[mi][ni][2] + bb0) * rl1;
                tot[mi][ni][3] += tanhf(acc[mi][ni][3] + bb1) * rl1;
            }
        }
    }

    // ---- store g_msgs ----
#pragma unroll
    for (int mi = 0; mi < 2; mi++) {
        int r = row0 + wm0 + mi * 16 + gid;
#pragma unroll
        for (int ni = 0; ni < 8; ni++) {
            int cb = col0 + wn0 + ni * 8 + tig * 2;
            if (r < BE)
                *(float2*)(g_msgs + (size_t)r * H_ + cb) =
                    make_float2(tot[mi][ni][0], tot[mi][ni][1]);
            if (r + 8 < BE)
                *(float2*)(g_msgs + (size_t)(r + 8) * H_ + cb) =
                    make_float2(tot[mi][ni][2], tot[mi][ni][3]);
        }
    }
}

// agg[b,r,:] = (1/49) * sum_{send != r} msgs[b, e(send,r), :]
__global__ void agg_kernel() {
    int idx = blockIdx.x * blockDim.x + threadIdx.x;
    if (idx >= BN * (H_ / 4)) return;
    int b = idx / (N_ * (H_ / 4));
    int rem = idx - b * (N_ * (H_ / 4));
    int r = rem / (H_ / 4);
    int h4 = rem - r * (H_ / 4);
    const float* base = g_msgs + (size_t)b * E_ * H_ + h4 * 4;
    float4 s = make_float4(0.f, 0.f, 0.f, 0.f);
    for (int send = 0; send < N_; send++) {
        if (send == r) continue;
        int e = send * 49 + r - (r > send);
        float4 v = *(const float4*)(base + (size_t)e * H_);
        s.x += v.x; s.y += v.y; s.z += v.z; s.w += v.w;
    }
    const float inv = 1.f / 49.f;
    s.x *= inv; s.y *= inv; s.z *= inv; s.w *= inv;
    *(float4*)(g_agg + (size_t)idx * 4) = s;
}

// GRU hidden-side GEMMs: grid (7,2,3)
__global__ __launch_bounds__(128, 4)
void gru_gemm(const float* __restrict__ w_hr,
              const float* __restrict__ w_hi,
              const float* __restrict__ w_hh) {
    __shared__ float As[16][68];
    __shared__ float Ws[16][132];
    int z = blockIdx.z;
    const float* W = (z == 0) ? w_hr : (z == 1) ? w_hi : w_hh;
    ull acc[8][4];
#pragma unroll
    for (int m = 0; m < 8; m++) { acc[m][0]=0; acc[m][1]=0; acc[m][2]=0; acc[m][3]=0; }
    int row0 = blockIdx.x * 64, col0 = blockIdx.y * 128;
    gemm64_core(g_agg, H_, W, H_, BN, H_, row0, col0, acc, As, Ws);
    gemm64_store(acc, nullptr, g_gru + (size_t)z * BN * H_, H_, BN, row0, col0, 0);
}

__device__ __forceinline__ float sigmoidf_(float x) { return 1.f / (1.f + expf(-x)); }

__global__ void gruew_kernel(const float* __restrict__ w_ir, const float* __restrict__ b_ir,
                             const float* __restrict__ w_ii, const float* __restrict__ b_ii,
                             const float* __restrict__ w_in, const float* __restrict__ b_in) {
    int idx = blockIdx.x * blockDim.x + threadIdx.x;
    if (idx >= BN * H_) return;
    int row = idx / H_, h = idx - row * H_;
    float xr = b_ir[h], xi = b_ii[h], xn = b_in[h];
#pragma unroll
    for (int f = 0; f < IN_; f++) {
        float iv = g_ins[row * IN_ + f];
        xr += iv * w_ir[h * IN_ + f];
        xi += iv * w_ii[h * IN_ + f];
        xn += iv * w_in[h * IN_ + f];
    }
    float ar = g_gru[idx];
    float ai = g_gru[BN * H_ + idx];
    float ah = g_gru[2 * BN * H_ + idx];
    float r  = sigmoidf_(xr + ar);
    float ig = sigmoidf_(xi + ai);
    float nn = tanhf(xn + r * ah);
    g_hidden[idx] = (1.f - ig) * nn + ig * g_hidden[idx];
}

__global__ __launch_bounds__(128, 4)
void p1_gemm(const float* __restrict__ w_o1, const float* __restrict__ b_o1) {
    __shared__ float As[16][68];
    __shared__ float Ws[16][132];
    ull acc[8][4];
#pragma unroll
    for (int m = 0; m < 8; m++) { acc[m][0]=0; acc[m][1]=0; acc[m][2]=0; acc[m][3]=0; }
    int row0 = blockIdx.x * 64, col0 = blockIdx.y * 128;
    gemm64_core(g_hidden, H_, w_o1, H_, BN, H_, row0, col0, acc, As, Ws);
    gemm64_store(acc, b_o1, g_p1, H_, BN, row0, col0, 1);
}
__global__ __launch_bounds__(128, 4)
void p2_gemm(const float* __restrict__ w_o2, const float* __restrict__ b_o2) {
    __shared__ float As[16][68];
    __shared__ float Ws[16][132];
    ull acc[8][4];
#pragma unroll
    for (int m = 0; m < 8; m++) { acc[m][0]=0; acc[m][1]=0; acc[m][2]=0; acc[m][3]=0; }
    int row0 = blockIdx.x * 64, col0 = blockIdx.y * 128;
    gemm64_core(g_p1, H_, w_o2, H_, BN, H_, row0, col0, acc, As, Ws);
    gemm64_store(acc, b_o2, g_p2, H_, BN, row0, col0, 1);
}

// pred = ins + p2 @ w_o3.T + b_o3; write out[:,t] and next ins
__global__ void f3_kernel(const float* __restrict__ w_o3,
                          const float* __restrict__ b_o3,
                          float* __restrict__ out, int t) {
    int row = blockIdx.x;                 // 0..399
    int w = threadIdx.x >> 5;             // 0..5
    int lane = threadIdx.x & 31;
    const float* pr = g_p2 + (size_t)row * H_;
    const float* wr = w_o3 + (size_t)w * H_;
    float s = 0.f;
    for (int j = lane; j < H_; j += 32) s += pr[j] * wr[j];
#pragma unroll
    for (int off = 16; off; off >>= 1) s += __shfl_down_sync(0xffffffffu, s, off);
    if (lane == 0) {
        int b = row / N_, n = row % N_;
        float v = g_ins[row * IN_ + w] + b_o3[w] + s;
        out[(((size_t)b * T_ + t) * N_ + n) * IN_ + w] = v;
        g_ins[row * IN_ + w] = v;
    }
}

// ---------------- launch -----------------------------------------------------
extern "C" void kernel_launch(void* const* d_in, const int* in_sizes, int n_in,
                              void* d_out, int out_size) {
    const float* inputs = (const float*)d_in[0];
    const float* edges  = (const float*)d_in[1];
    const float* msg_w1 = (const float*)d_in[2];
    const float* msg_b1 = (const float*)d_in[3];
    const float* msg_w2 = (const float*)d_in[4];
    const float* msg_b2 = (const float*)d_in[5];
    const float* w_hr = (const float*)d_in[6];
    const float* w_hi = (const float*)d_in[7];
    const float* w_hh = (const float*)d_in[8];
    const float* w_ir = (const float*)d_in[9];
    const float* b_ir = (const float*)d_in[10];
    const float* w_ii = (const float*)d_in[11];
    const float* b_ii = (const float*)d_in[12];
    const float* w_in_ = (const float*)d_in[13];
    const float* b_in_ = (const float*)d_in[14];
    const float* w_o1 = (const float*)d_in[15];
    const float* b_o1 = (const float*)d_in[16];
    const float* w_o2 = (const float*)d_in[17];
    const float* b_o2 = (const float*)d_in[18];
    const float* w_o3 = (const float*)d_in[19];
    const float* b_o3 = (const float*)d_in[20];
    float* out = (float*)d_out;

    init_kernel<<<(BN * H_ + 255) / 256, 256>>>(inputs);

    const int rowt = (BE + 63) / 64;  // 307
    for (int t = 0; t < T_; t++) {
        urus_kernel<<<dim3(7, 2, 6), 128>>>(msg_w1);
        msgs_tc_kernel<<<dim3(rowt, 2), 128>>>(msg_w2, msg_b1, msg_b2, edges, t);
        agg_kernel<<<(BN * (H_ / 4) + 255) / 256, 256>>>();
        gru_gemm<<<dim3(7, 2, 3), 128>>>(w_hr, w_hi, w_hh);
        gruew_kernel<<<(BN * H_ + 255) / 256, 256>>>(w_ir, b_ir, w_ii, b_ii, w_in_, b_in_);
        p1_gemm<<<dim3(7, 2), 128>>>(w_o1, b_o1);
        p2_gemm<<<dim3(7, 2), 128>>>(w_o2, b_o2);
        f3_kernel<<<BN, 192>>>(w_o3, b_o3, out, t);
    }
}

// round 4
// speedup vs baseline: 1.7937x; 1.2074x over previous
#include <cuda_runtime.h>
#include <math.h>

#define B_  8
#define T_  10
#define N_  50
#define IN_ 6
#define H_  256
#define K_  4
#define E_  2450           // N*(N-1)
#define BN  400            // B*N
#define BE  19600          // B*E

// ---------------- scratch (device globals) ----------------------------------
__device__ float g_hidden[BN * H_];
__device__ float g_ins[BN * IN_];
__device__ float g_U[6 * BN * H_];          // (type-1)*2 + {recv=0,send=1}
__device__ float g_msgs[BE * H_];           // type-summed weighted messages
__device__ float g_agg[BN * H_];
__device__ float g_gru[3 * BN * H_];
__device__ float g_p1[BN * H_];
__device__ float g_p2[BN * H_];

// ---------------- tf32 mma helpers ------------------------------------------
__device__ __forceinline__ unsigned tf32c(float x) {
    unsigned r; asm("cvt.rna.tf32.f32 %0, %1;" : "=r"(r) : "f"(x)); return r;
}
__device__ __forceinline__ void mma8(float c[4], const unsigned a[4],
                                     unsigned b0, unsigned b1) {
    asm volatile(
        "mma.sync.aligned.m16n8k8.row.col.f32.tf32.tf32.f32 "
        "{%0,%1,%2,%3}, {%4,%5,%6,%7}, {%8,%9}, {%0,%1,%2,%3};"
        : "+f"(c[0]), "+f"(c[1]), "+f"(c[2]), "+f"(c[3])
        : "r"(a[0]), "r"(a[1]), "r"(a[2]), "r"(a[3]), "r"(b0), "r"(b1));
}

// ---------------- generic tf32 GEMM tile kernel body ------------------------
// 128 threads = 4 warps (2m x 2n), block tile 64(M) x 128(N), K mult of 16.
// C[tile] = A @ W^T (+bias, +relu). A:[M,K] lda row-major; W:[N,K] ldw row-major.
// Requires col0+128 <= N of W.
template<int ACT>
__device__ __forceinline__ void tc_gemm64(
    const float* __restrict__ A, int lda,
    const float* __restrict__ W, int ldw,
    const float* __restrict__ bias,
    float* __restrict__ C, int ldc,
    int M, int Kdim, int row0, int col0)
{
    __shared__ unsigned As[64][20];
    __shared__ unsigned Ws[128][20];

    const int tid = threadIdx.x;
    const int lane = tid & 31, wid = tid >> 5;
    const int gid = lane >> 2, tig = lane & 3;
    const int wm0 = (wid >> 1) * 32, wn0 = (wid & 1) * 64;
    const int ar = tid >> 1, akq = (tid & 1) * 8;
    const int wn = tid;

    float acc[2][8][4];
#pragma unroll
    for (int mi = 0; mi < 2; mi++)
#pragma unroll
        for (int ni = 0; ni < 8; ni++)
#pragma unroll
            for (int j = 0; j < 4; j++) acc[mi][ni][j] = 0.f;

    int arow = row0 + ar; if (arow >= M) arow = M - 1;
    const float* Ap = A + (size_t)arow * lda + akq;
    const float* Wp = W + (size_t)(col0 + wn) * ldw;

    float4 pa0, pa1, pw0, pw1, pw2, pw3;
    pa0 = *(const float4*)(Ap);     pa1 = *(const float4*)(Ap + 4);
    pw0 = *(const float4*)(Wp);     pw1 = *(const float4*)(Wp + 4);
    pw2 = *(const float4*)(Wp + 8); pw3 = *(const float4*)(Wp + 12);

    const int nchunks = Kdim / 16;
#pragma unroll 1
    for (int c = 0; c < nchunks; c++) {
        __syncthreads();
        uint4 av0, av1;
        av0.x = tf32c(pa0.x); av0.y = tf32c(pa0.y); av0.z = tf32c(pa0.z); av0.w = tf32c(pa0.w);
        av1.x = tf32c(pa1.x); av1.y = tf32c(pa1.y); av1.z = tf32c(pa1.z); av1.w = tf32c(pa1.w);
        *(uint4*)&As[ar][akq]     = av0;
        *(uint4*)&As[ar][akq + 4] = av1;
        uint4 w0v, w1v, w2v, w3v;
        w0v.x = tf32c(pw0.x); w0v.y = tf32c(pw0.y); w0v.z = tf32c(pw0.z); w0v.w = tf32c(pw0.w);
        w1v.x = tf32c(pw1.x); w1v.y = tf32c(pw1.y); w1v.z = tf32c(pw1.z); w1v.w = tf32c(pw1.w);
        w2v.x = tf32c(pw2.x); w2v.y = tf32c(pw2.y); w2v.z = tf32c(pw2.z); w2v.w = tf32c(pw2.w);
        w3v.x = tf32c(pw3.x); w3v.y = tf32c(pw3.y); w3v.z = tf32c(pw3.z); w3v.w = tf32c(pw3.w);
        *(uint4*)&Ws[wn][0]  = w0v;
        *(uint4*)&Ws[wn][4]  = w1v;
        *(uint4*)&Ws[wn][8]  = w2v;
        *(uint4*)&Ws[wn][12] = w3v;
        __syncthreads();
        if (c + 1 < nchunks) {
            int k0 = (c + 1) * 16;
            pa0 = *(const float4*)(Ap + k0);     pa1 = *(const float4*)(Ap + k0 + 4);
            pw0 = *(const float4*)(Wp + k0);     pw1 = *(const float4*)(Wp + k0 + 4);
            pw2 = *(const float4*)(Wp + k0 + 8); pw3 = *(const float4*)(Wp + k0 + 12);
        }
#pragma unroll
        for (int kk = 0; kk < 16; kk += 8) {
            unsigned a0[4], a1[4];
            a0[0] = As[wm0 + gid][kk + tig];
            a0[1] = As[wm0 + gid + 8][kk + tig];
            a0[2] = As[wm0 + gid][kk + tig + 4];
            a0[3] = As[wm0 + gid + 8][kk + tig + 4];
            a1[0] = As[wm0 + 16 + gid][kk + tig];
            a1[1] = As[wm0 + 24 + gid][kk + tig];
            a1[2] = As[wm0 + 16 + gid][kk + tig + 4];
            a1[3] = As[wm0 + 24 + gid][kk + tig + 4];
#pragma unroll
            for (int ni = 0; ni < 8; ni++) {
                int nr = wn0 + ni * 8 + gid;
                unsigned b0 = Ws[nr][kk + tig];
                unsigned b1 = Ws[nr][kk + tig + 4];
                mma8(acc[0][ni], a0, b0, b1);
                mma8(acc[1][ni], a1, b0, b1);
            }
        }
    }

#pragma unroll
    for (int mi = 0; mi < 2; mi++) {
        int r = row0 + wm0 + mi * 16 + gid;
#pragma unroll
        for (int ni = 0; ni < 8; ni++) {
            int cb = col0 + wn0 + ni * 8 + tig * 2;
            float b0 = 0.f, b1 = 0.f;
            if (bias) { b0 = bias[cb]; b1 = bias[cb + 1]; }
            float v0 = acc[mi][ni][0] + b0, v1 = acc[mi][ni][1] + b1;
            float v2 = acc[mi][ni][2] + b0, v3 = acc[mi][ni][3] + b1;
            if (ACT == 1) {
                v0 = fmaxf(v0, 0.f); v1 = fmaxf(v1, 0.f);
                v2 = fmaxf(v2, 0.f); v3 = fmaxf(v3, 0.f);
            }
            if (r < M)     *(float2*)(C + (size_t)r * ldc + cb)       = make_float2(v0, v1);
            if (r + 8 < M) *(float2*)(C + (size_t)(r + 8) * ldc + cb) = make_float2(v2, v3);
        }
    }
}

// ---------------- kernels ----------------------------------------------------

__global__ void init_kernel(const float* __restrict__ inputs) {
    int idx = blockIdx.x * blockDim.x + threadIdx.x;
    if (idx < BN * H_) g_hidden[idx] = 0.f;
    if (idx < BN * IN_) {
        int row = idx / IN_, c = idx % IN_;
        int b = row / N_, n = row % N_;
        g_ins[idx] = inputs[(((size_t)b * T_ + 0) * N_ + n) * IN_ + c];
    }
}

// Ur/Us via tensor cores: grid (7, 2, 6): z = (type-1)*2 + rs
__global__ __launch_bounds__(128)
void urus_tc(const float* __restrict__ msg_w1) {
    int z = blockIdx.z;
    int it = z >> 1, rs = z & 1;
    const float* W = msg_w1 + (size_t)(it + 1) * H_ * 2 * H_ + rs * H_;
    tc_gemm64<0>(g_hidden, H_, W, 2 * H_, nullptr,
                 g_U + (size_t)z * BN * H_, H_,
                 BN, H_, blockIdx.x * 64, blockIdx.y * 128);
}

// ======== fused edge-message kernel (tf32 tensor cores) ======================
__global__ __launch_bounds__(128)
void msgs_tc_kernel(const float* __restrict__ msg_w2,
                    const float* __restrict__ msg_b1,
                    const float* __restrict__ msg_b2,
                    const float* __restrict__ edges, int t)
{
    __shared__ unsigned As[64][20];
    __shared__ unsigned Ws[128][20];
    __shared__ float relw[64];
    __shared__ float b2s[128];
    __shared__ int rrow[64], srow[64], eoff[64];

    const int tid = threadIdx.x;
    const int lane = tid & 31, wid = tid >> 5;
    const int gid = lane >> 2, tig = lane & 3;
    const int wm0 = (wid >> 1) * 32, wn0 = (wid & 1) * 64;
    const int row0 = blockIdx.x * 64, col0 = blockIdx.y * 128;

    if (tid < 64) {
        int r = row0 + tid;
        int valid = (r < BE);
        if (!valid) r = BE - 1;
        int b = r / E_;
        int e = r - b * E_;
        int send = e / 49, rr2 = e - send * 49;
        int recv = rr2 + (rr2 >= send);
        srow[tid] = b * N_ + send;
        rrow[tid] = b * N_ + recv;
        eoff[tid] = valid ? (((b * T_ + t) * E_ + e) * K_) : -1;
    }
    __syncthreads();

    const int ar  = tid >> 1;
    const int akq = (tid & 1) * 8;
    const int wn  = tid;

    float tot[2][8][4];
#pragma unroll
    for (int mi = 0; mi < 2; mi++)
#pragma unroll
        for (int ni = 0; ni < 8; ni++)
#pragma unroll
            for (int j = 0; j < 4; j++) tot[mi][ni][j] = 0.f;

    for (int z = 0; z < 3; z++) {
        const int type = z + 1;
        __syncthreads();
        if (tid < 64)
            relw[tid] = (eoff[tid] >= 0) ? edges[eoff[tid] + type] * (1.f / 3.f) : 0.f;
        if (tid < 128)
            b2s[tid] = msg_b2[(size_t)type * H_ + col0 + tid];

        float acc[2][8][4];
#pragma unroll
        for (int mi = 0; mi < 2; mi++)
#pragma unroll
            for (int ni = 0; ni < 8; ni++)
#pragma unroll
                for (int j = 0; j < 4; j++) acc[mi][ni][j] = 0.f;

        const float* Ur = g_U + ((size_t)(2 * z) * BN + rrow[ar]) * H_ + akq;
        const float* Us = g_U + ((size_t)(2 * z + 1) * BN + srow[ar]) * H_ + akq;
        const float* Wb = msg_w2 + ((size_t)type * H_ + (col0 + wn)) * H_;
        const float* B1 = msg_b1 + (size_t)type * H_ + akq;

        float4 pu0, pu1, ps0, ps1, pw0, pw1, pw2, pw3, pb0, pb1;
        pu0 = *(const float4*)(Ur);     pu1 = *(const float4*)(Ur + 4);
        ps0 = *(const float4*)(Us);     ps1 = *(const float4*)(Us + 4);
        pw0 = *(const float4*)(Wb);     pw1 = *(const float4*)(Wb + 4);
        pw2 = *(const float4*)(Wb + 8); pw3 = *(const float4*)(Wb + 12);
        pb0 = *(const float4*)(B1);     pb1 = *(const float4*)(B1 + 4);

#pragma unroll 1
        for (int c = 0; c < 16; c++) {
            __syncthreads();
            uint4 a0v, a1v;
            a0v.x = tf32c(tanhf(pu0.x + ps0.x + pb0.x));
            a0v.y = tf32c(tanhf(pu0.y + ps0.y + pb0.y));
            a0v.z = tf32c(tanhf(pu0.z + ps0.z + pb0.z));
            a0v.w = tf32c(tanhf(pu0.w + ps0.w + pb0.w));
            a1v.x = tf32c(tanhf(pu1.x + ps1.x + pb1.x));
            a1v.y = tf32c(tanhf(pu1.y + ps1.y + pb1.y));
            a1v.z = tf32c(tanhf(pu1.z + ps1.z + pb1.z));
            a1v.w = tf32c(tanhf(pu1.w + ps1.w + pb1.w));
            *(uint4*)&As[ar][akq]     = a0v;
            *(uint4*)&As[ar][akq + 4] = a1v;
            uint4 w0v, w1v, w2v, w3v;
            w0v.x = tf32c(pw0.x); w0v.y = tf32c(pw0.y); w0v.z = tf32c(pw0.z); w0v.w = tf32c(pw0.w);
            w1v.x = tf32c(pw1.x); w1v.y = tf32c(pw1.y); w1v.z = tf32c(pw1.z); w1v.w = tf32c(pw1.w);
            w2v.x = tf32c(pw2.x); w2v.y = tf32c(pw2.y); w2v.z = tf32c(pw2.z); w2v.w = tf32c(pw2.w);
            w3v.x = tf32c(pw3.x); w3v.y = tf32c(pw3.y); w3v.z = tf32c(pw3.z); w3v.w = tf32c(pw3.w);
            *(uint4*)&Ws[wn][0]  = w0v;
            *(uint4*)&Ws[wn][4]  = w1v;
            *(uint4*)&Ws[wn][8]  = w2v;
            *(uint4*)&Ws[wn][12] = w3v;
            __syncthreads();
            if (c < 15) {
                int k0 = (c + 1) * 16;
                pu0 = *(const float4*)(Ur + k0);     pu1 = *(const float4*)(Ur + k0 + 4);
                ps0 = *(const float4*)(Us + k0);     ps1 = *(const float4*)(Us + k0 + 4);
                pw0 = *(const float4*)(Wb + k0);     pw1 = *(const float4*)(Wb + k0 + 4);
                pw2 = *(const float4*)(Wb + k0 + 8); pw3 = *(const float4*)(Wb + k0 + 12);
                pb0 = *(const float4*)(B1 + k0);     pb1 = *(const float4*)(B1 + k0 + 4);
            }
#pragma unroll
            for (int kk = 0; kk < 16; kk += 8) {
                unsigned a0[4], a1[4];
                a0[0] = As[wm0 + gid][kk + tig];
                a0[1] = As[wm0 + gid + 8][kk + tig];
                a0[2] = As[wm0 + gid][kk + tig + 4];
                a0[3] = As[wm0 + gid + 8][kk + tig + 4];
                a1[0] = As[wm0 + 16 + gid][kk + tig];
                a1[1] = As[wm0 + 24 + gid][kk + tig];
                a1[2] = As[wm0 + 16 + gid][kk + tig + 4];
                a1[3] = As[wm0 + 24 + gid][kk + tig + 4];
#pragma unroll
                for (int ni = 0; ni < 8; ni++) {
                    int nr = wn0 + ni * 8 + gid;
                    unsigned b0 = Ws[nr][kk + tig];
                    unsigned b1 = Ws[nr][kk + tig + 4];
                    mma8(acc[0][ni], a0, b0, b1);
                    mma8(acc[1][ni], a1, b0, b1);
                }
            }
        }

#pragma unroll
        for (int mi = 0; mi < 2; mi++) {
            float rl0 = relw[wm0 + mi * 16 + gid];
            float rl1 = relw[wm0 + mi * 16 + gid + 8];
#pragma unroll
            for (int ni = 0; ni < 8; ni++) {
                int cl = wn0 + ni * 8 + tig * 2;
                float bb0 = b2s[cl], bb1 = b2s[cl + 1];
                tot[mi][ni][0] += tanhf(acc[mi][ni][0] + bb0) * rl0;
                tot[mi][ni][1] += tanhf(acc[mi][ni][1] + bb1) * rl0;
                tot[mi][ni][2] += tanhf(acc[mi][ni][2] + bb0) * rl1;
                tot[mi][ni][3] += tanhf(acc[mi][ni][3] + bb1) * rl1;
            }
        }
    }

#pragma unroll
    for (int mi = 0; mi < 2; mi++) {
        int r = row0 + wm0 + mi * 16 + gid;
#pragma unroll
        for (int ni = 0; ni < 8; ni++) {
            int cb = col0 + wn0 + ni * 8 + tig * 2;
            if (r < BE)
                *(float2*)(g_msgs + (size_t)r * H_ + cb) =
                    make_float2(tot[mi][ni][0], tot[mi][ni][1]);
            if (r + 8 < BE)
                *(float2*)(g_msgs + (size_t)(r + 8) * H_ + cb) =
                    make_float2(tot[mi][ni][2], tot[mi][ni][3]);
        }
    }
}

// agg: grid = BN blocks, 256 threads; 4-way send split + deterministic combine
__global__ __launch_bounds__(256)
void agg_kernel() {
    __shared__ float part[3][256];          // partials for send-groups 1..3
    const int tid = threadIdx.x;
    const int sg = tid >> 6;                // 0..3
    const int hq = tid & 63;                // h quad 0..63
    const int row = blockIdx.x;             // b*N + r
    const int b = row / N_, r = row - b * N_;
    const float* base = g_msgs + (size_t)b * E_ * H_ + hq * 4;
    float4 s = make_float4(0.f, 0.f, 0.f, 0.f);
    for (int send = sg; send < N_; send += 4) {
        if (send == r) continue;
        int e = send * 49 + r - (r > send);
        float4 v = *(const float4*)(base + (size_t)e * H_);
        s.x += v.x; s.y += v.y; s.z += v.z; s.w += v.w;
    }
    if (sg > 0) *(float4*)&part[sg - 1][hq * 4] = s;
    __syncthreads();
    if (sg == 0) {
        const float4 p0 = *(const float4*)&part[0][hq * 4];
        const float4 p1 = *(const float4*)&part[1][hq * 4];
        const float4 p2 = *(const float4*)&part[2][hq * 4];
        const float inv = 1.f / 49.f;
        float4 o;
        o.x = (s.x + p0.x + p1.x + p2.x) * inv;
        o.y = (s.y + p0.y + p1.y + p2.y) * inv;
        o.z = (s.z + p0.z + p1.z + p2.z) * inv;
        o.w = (s.w + p0.w + p1.w + p2.w) * inv;
        *(float4*)(g_agg + (size_t)row * H_ + hq * 4) = o;
    }
}

// GRU hidden-side GEMMs (tensor cores): grid (7,2,3)
__global__ __launch_bounds__(128)
void gru_tc(const float* __restrict__ w_hr,
            const float* __restrict__ w_hi,
            const float* __restrict__ w_hh) {
    int z = blockIdx.z;
    const float* W = (z == 0) ? w_hr : (z == 1) ? w_hi : w_hh;
    tc_gemm64<0>(g_agg, H_, W, H_, nullptr,
                 g_gru + (size_t)z * BN * H_, H_,
                 BN, H_, blockIdx.x * 64, blockIdx.y * 128);
}

__device__ __forceinline__ float sigmoidf_(float x) { return 1.f / (1.f + expf(-x)); }

__global__ void gruew_kernel(const float* __restrict__ w_ir, const float* __restrict__ b_ir,
                             const float* __restrict__ w_ii, const float* __restrict__ b_ii,
                             const float* __restrict__ w_in, const float* __restrict__ b_in) {
    int idx = blockIdx.x * blockDim.x + threadIdx.x;
    if (idx >= BN * H_) return;
    int row = idx / H_, h = idx - row * H_;
    float xr = b_ir[h], xi = b_ii[h], xn = b_in[h];
#pragma unroll
    for (int f = 0; f < IN_; f++) {
        float iv = g_ins[row * IN_ + f];
        xr += iv * w_ir[h * IN_ + f];
        xi += iv * w_ii[h * IN_ + f];
        xn += iv * w_in[h * IN_ + f];
    }
    float ar = g_gru[idx];
    float ai = g_gru[BN * H_ + idx];
    float ah = g_gru[2 * BN * H_ + idx];
    float r  = sigmoidf_(xr + ar);
    float ig = sigmoidf_(xi + ai);
    float nn = tanhf(xn + r * ah);
    g_hidden[idx] = (1.f - ig) * nn + ig * g_hidden[idx];
}

__global__ __launch_bounds__(128)
void p1_tc(const float* __restrict__ w_o1, const float* __restrict__ b_o1) {
    tc_gemm64<1>(g_hidden, H_, w_o1, H_, b_o1, g_p1, H_,
                 BN, H_, blockIdx.x * 64, blockIdx.y * 128);
}
__global__ __launch_bounds__(128)
void p2_tc(const float* __restrict__ w_o2, const float* __restrict__ b_o2) {
    tc_gemm64<1>(g_p1, H_, w_o2, H_, b_o2, g_p2, H_,
                 BN, H_, blockIdx.x * 64, blockIdx.y * 128);
}

// pred = ins + p2 @ w_o3.T + b_o3; write out[:,t] and next ins
__global__ void f3_kernel(const float* __restrict__ w_o3,
                          const float* __restrict__ b_o3,
                          float* __restrict__ out, int t) {
    int row = blockIdx.x;                 // 0..399
    int w = threadIdx.x >> 5;             // 0..5
    int lane = threadIdx.x & 31;
    const float* pr = g_p2 + (size_t)row * H_;
    const float* wr = w_o3 + (size_t)w * H_;
    float s = 0.f;
    for (int j = lane; j < H_; j += 32) s += pr[j] * wr[j];
#pragma unroll
    for (int off = 16; off; off >>= 1) s += __shfl_down_sync(0xffffffffu, s, off);
    if (lane == 0) {
        int b = row / N_, n = row % N_;
        float v = g_ins[row * IN_ + w] + b_o3[w] + s;
        out[(((size_t)b * T_ + t) * N_ + n) * IN_ + w] = v;
        g_ins[row * IN_ + w] = v;
    }
}

// ---------------- launch -----------------------------------------------------
extern "C" void kernel_launch(void* const* d_in, const int* in_sizes, int n_in,
                              void* d_out, int out_size) {
    const float* inputs = (const float*)d_in[0];
    const float* edges  = (const float*)d_in[1];
    const float* msg_w1 = (const float*)d_in[2];
    const float* msg_b1 = (const float*)d_in[3];
    const float* msg_w2 = (const float*)d_in[4];
    const float* msg_b2 = (const float*)d_in[5];
    const float* w_hr = (const float*)d_in[6];
    const float* w_hi = (const float*)d_in[7];
    const float* w_hh = (const float*)d_in[8];
    const float* w_ir = (const float*)d_in[9];
    const float* b_ir = (const float*)d_in[10];
    const float* w_ii = (const float*)d_in[11];
    const float* b_ii = (const float*)d_in[12];
    const float* w_in_ = (const float*)d_in[13];
    const float* b_in_ = (const float*)d_in[14];
    const float* w_o1 = (const float*)d_in[15];
    const float* b_o1 = (const float*)d_in[16];
    const float* w_o2 = (const float*)d_in[17];
    const float* b_o2 = (const float*)d_in[18];
    const float* w_o3 = (const float*)d_in[19];
    const float* b_o3 = (const float*)d_in[20];
    float* out = (float*)d_out;

    init_kernel<<<(BN * H_ + 255) / 256, 256>>>(inputs);

    const int rowt = (BE + 63) / 64;  // 307
    for (int t = 0; t < T_; t++) {
        urus_tc<<<dim3(7, 2, 6), 128>>>(msg_w1);
        msgs_tc_kernel<<<dim3(rowt, 2), 128>>>(msg_w2, msg_b1, msg_b2, edges, t);
        agg_kernel<<<BN, 256>>>();
        gru_tc<<<dim3(7, 2, 3), 128>>>(w_hr, w_hi, w_hh);
        gruew_kernel<<<(BN * H_ + 255) / 256, 256>>>(w_ir, b_ir, w_ii, b_ii, w_in_, b_in_);
        p1_tc<<<dim3(7, 2), 128>>>(w_o1, b_o1);
        p2_tc<<<dim3(7, 2), 128>>>(w_o2, b_o2);
        f3_kernel<<<BN, 192>>>(w_o3, b_o3, out, t);
    }
}